// round 5
// baseline (speedup 1.0000x reference)
#include <cuda_runtime.h>
#include <math.h>
#include <stdint.h>

#define TTOK   2048
#define HDIM   768
#define NEXP   8
#define IDIM   768
#define MAXP   (TTOK*2)
#define ALPHA  1.702f
#define LIMIT  7.0f
#define BK     32
#define NCH    (HDIM / BK)   // 24

// Tiles: A 128x32 fp32 (stride 36), B 32x128 fp32 (stride 136)
#define A_STRIDE 36
#define B_STRIDE 136
#define A_BYTES  (128 * A_STRIDE * 4)     // 18432
#define B_BYTES  (BK * B_STRIDE * 4)      // 17408
#define STAGE    (A_BYTES + B_BYTES)      // 35840
#define SM_TOTAL (3 * STAGE)              // 107520

// -------- scratch --------
__device__ int   g_cnt[NEXP];
__device__ int   g_list[NEXP * MAXP];
__device__ float g_w[TTOK * 2];
__device__ float g_act[(size_t)TTOK * 2 * IDIM];   // tf32-rounded

// ------------------------- helpers -------------------------
__device__ __forceinline__ uint32_t tf32u(float x) {
    uint32_t u;
    asm("cvt.rna.tf32.f32 %0, %1;" : "=r"(u) : "f"(x));
    return u;
}
__device__ __forceinline__ float to_tf32f(float x) { return __uint_as_float(tf32u(x)); }
__device__ __forceinline__ void mma8(float* d, const uint32_t* a, const uint32_t* b) {
    asm volatile(
        "mma.sync.aligned.m16n8k8.row.col.f32.tf32.tf32.f32 "
        "{%0,%1,%2,%3}, {%4,%5,%6,%7}, {%8,%9}, {%0,%1,%2,%3};"
        : "+f"(d[0]), "+f"(d[1]), "+f"(d[2]), "+f"(d[3])
        : "r"(a[0]), "r"(a[1]), "r"(a[2]), "r"(a[3]), "r"(b[0]), "r"(b[1]));
}
__device__ __forceinline__ uint32_t smem_u32(const void* p) {
    uint32_t a;
    asm("{ .reg .u64 t; cvta.to.shared.u64 t, %1; cvt.u32.u64 %0, t; }"
        : "=r"(a) : "l"(p));
    return a;
}
__device__ __forceinline__ void cp16(uint32_t dst, const void* src, int sz) {
    asm volatile("cp.async.cg.shared.global [%0], [%1], 16, %2;"
                 :: "r"(dst), "l"(src), "r"(sz));
}
#define CP_COMMIT() asm volatile("cp.async.commit_group;" ::: "memory")
#define CP_WAIT(n)  asm volatile("cp.async.wait_group %0;" :: "n"(n) : "memory")
__device__ __forceinline__ void ldsm4(uint32_t* r, uint32_t addr) {
    asm volatile("ldmatrix.sync.aligned.m8n8.x4.shared.b16 {%0,%1,%2,%3}, [%4];"
                 : "=r"(r[0]), "=r"(r[1]), "=r"(r[2]), "=r"(r[3]) : "r"(addr));
}

// ---------------- shared mainloop (block 128x128, warp 64x32) ----------------
// Warps: 8 = 2(M) x 4(N). acc[mt<4][nt<4][4].
template<bool CVT_A>
__device__ __forceinline__ void run_mainloop(
    char* dsm,
    const float* const* aSrc, const int* aSz, const uint32_t* aDst,
    const float* const* bSrc, const uint32_t* bDst, int bLd,
    float acc[4][4][4], int wM, int wN, int lane)
{
    uint32_t smb = smem_u32(dsm);
    int gID = lane >> 2, tg = lane & 3;
    // ldmatrix per-thread address offset within A tile
    uint32_t aOff = (uint32_t)(((wM * 64 + (lane & 15)) * A_STRIDE + (lane >> 4) * 4) * 4);

#define ML_ISSUE(c) do {                                                       \
    uint32_t st = smb + (uint32_t)((c) % 3) * STAGE;                           \
    int k0 = (c) * BK;                                                         \
    _Pragma("unroll")                                                          \
    for (int i = 0; i < 4; i++) cp16(st + aDst[i], aSrc[i] + k0, aSz[i]);      \
    _Pragma("unroll")                                                          \
    for (int i = 0; i < 4; i++)                                                \
        cp16(st + A_BYTES + bDst[i], bSrc[i] + (size_t)k0 * bLd, 16);          \
    } while (0)

    ML_ISSUE(0); CP_COMMIT();
    ML_ISSUE(1); CP_COMMIT();

    for (int c = 0; c < NCH; c++) {
        CP_WAIT(1);
        __syncthreads();
        if (c + 2 < NCH) ML_ISSUE(c + 2);
        CP_COMMIT();

        uint32_t stA = smb + (uint32_t)(c % 3) * STAGE;
        const float* fB = (const float*)(dsm + (c % 3) * STAGE + A_BYTES);

#pragma unroll
        for (int k8 = 0; k8 < 4; k8++) {
            int k = k8 * 8;
            uint32_t a[4][4];
#pragma unroll
            for (int mt = 0; mt < 4; mt++) {
                ldsm4(a[mt], stA + aOff + (uint32_t)(mt * 16 * A_STRIDE * 4 + k8 * 32));
                if (CVT_A) {
#pragma unroll
                    for (int q = 0; q < 4; q++)
                        a[mt][q] = tf32u(__uint_as_float(a[mt][q]));
                }
            }
#pragma unroll
            for (int nt = 0; nt < 4; nt++) {
                int col = wN * 32 + nt * 8 + gID;
                uint32_t b[2];
                b[0] = tf32u(fB[(k + tg) * B_STRIDE + col]);
                b[1] = tf32u(fB[(k + tg + 4) * B_STRIDE + col]);
#pragma unroll
                for (int mt = 0; mt < 4; mt++)
                    mma8(acc[mt][nt], a[mt], b);
            }
        }
    }
#undef ML_ISSUE
}

// ------------------------------ init ------------------------------
__global__ __launch_bounds__(256) void init_kernel(float* __restrict__ out)
{
    int idx = blockIdx.x * 256 + threadIdx.x;
    if (idx < NEXP) g_cnt[idx] = 0;
    if (idx < TTOK * HDIM / 4)
        ((float4*)out)[idx] = make_float4(0.f, 0.f, 0.f, 0.f);
}

// ------------------------------ router ------------------------------
__global__ __launch_bounds__(256) void router_kernel(
    const float* __restrict__ x, const float* __restrict__ Wr,
    const float* __restrict__ br)
{
    int warp = threadIdx.x >> 5;
    int lane = threadIdx.x & 31;
    int t = blockIdx.x * 8 + warp;
    if (t >= TTOK) return;

    const float4* xr = (const float4*)(x + (size_t)t * HDIM);
    float acc[NEXP];
#pragma unroll
    for (int e = 0; e < NEXP; e++) acc[e] = 0.f;

    for (int h4 = lane; h4 < HDIM / 4; h4 += 32) {
        float4 xv = xr[h4];
        const float* w = Wr + h4 * 4 * NEXP;
#pragma unroll
        for (int e = 0; e < NEXP; e++) {
            float s = fmaf(xv.x, w[e], 0.f);
            s = fmaf(xv.y, w[e + 8], s);
            s = fmaf(xv.z, w[e + 16], s);
            s = fmaf(xv.w, w[e + 24], s);
            acc[e] += s;
        }
    }
#pragma unroll
    for (int e = 0; e < NEXP; e++) {
#pragma unroll
        for (int o = 16; o > 0; o >>= 1)
            acc[e] += __shfl_xor_sync(0xffffffffu, acc[e], o);
    }
    if (lane == 0) {
#pragma unroll
        for (int e = 0; e < NEXP; e++) acc[e] += br[e];

        int i0 = 0; float v0 = acc[0];
#pragma unroll
        for (int e = 1; e < NEXP; e++)
            if (acc[e] > v0) { v0 = acc[e]; i0 = e; }
        int i1 = -1; float v1 = -INFINITY;
#pragma unroll
        for (int e = 0; e < NEXP; e++)
            if (e != i0 && acc[e] > v1) { v1 = acc[e]; i1 = e; }

        float s1 = expf(v1 - v0);
        float d  = 1.f + s1;
        g_w[t * 2 + 0] = 1.f / d;
        g_w[t * 2 + 1] = s1 / d;

        int p0 = atomicAdd(&g_cnt[i0], 1);
        g_list[i0 * MAXP + p0] = t * 2;
        int p1 = atomicAdd(&g_cnt[i1], 1);
        g_list[i1 * MAXP + p1] = t * 2 + 1;
    }
}

// =============== stage 1: gate/up GEMM (N=128: [gate64|up64]) + SwiGLU ===============
__global__ __launch_bounds__(256, 2) void gu_mma(
    const float* __restrict__ x, const float* __restrict__ Wgu,
    const float* __restrict__ bgu)
{
    int e   = blockIdx.z;
    int cnt = g_cnt[e];
    int m0  = blockIdx.y * 128;
    if (m0 >= cnt) return;
    int n0  = blockIdx.x * 64;    // gate-plane column base

    extern __shared__ __align__(16) char dsm[];
    __shared__ int sSlot[128];

    int tid  = threadIdx.x;
    int wid  = tid >> 5, lane = tid & 31;
    int wM   = wid >> 2, wN = wid & 3;
    int gID  = lane >> 2, tg = lane & 3;

    for (int m = tid; m < 128; m += 256) {
        int idx = m0 + m;
        sSlot[m] = (idx < cnt) ? g_list[e * MAXP + idx] : -1;
    }
    __syncthreads();

    const float* Wg = Wgu + (size_t)e * HDIM * (2 * IDIM);

    const float* aSrc[4]; int aSz[4]; uint32_t aDst[4];
#pragma unroll
    for (int i = 0; i < 4; i++) {
        int idx = tid + i * 256;
        int m = idx >> 3, kq = idx & 7;
        int slot = sSlot[m];
        aSrc[i] = (slot >= 0) ? x + (size_t)(slot >> 1) * HDIM + kq * 4 : x;
        aSz[i]  = (slot >= 0) ? 16 : 0;
        aDst[i] = (uint32_t)(m * A_STRIDE + kq * 4) * 4u;
    }
    const float* bSrc[4]; uint32_t bDst[4];
#pragma unroll
    for (int i = 0; i < 4; i++) {
        int idx = tid + i * 256;
        int k = idx >> 5, n4 = idx & 31;
        int gcol = (n4 < 16) ? (n0 + n4 * 4) : (IDIM + n0 + (n4 - 16) * 4);
        bSrc[i] = Wg + (size_t)k * (2 * IDIM) + gcol;
        bDst[i] = (uint32_t)(k * B_STRIDE + n4 * 4) * 4u;
    }

    float acc[4][4][4];
#pragma unroll
    for (int mt = 0; mt < 4; mt++)
#pragma unroll
        for (int nt = 0; nt < 4; nt++)
#pragma unroll
            for (int q = 0; q < 4; q++) acc[mt][nt][q] = 0.f;

    run_mainloop<true>(dsm, aSrc, aSz, aDst, bSrc, bDst, 2 * IDIM,
                       acc, wM, wN, lane);

    // ---- epilogue: gate warps (wN<2) compute glu -> smem; up warps finish ----
    __syncthreads();
    float* sG = (float*)dsm;   // [128][68]
    const float* bge = bgu + (size_t)e * (2 * IDIM);

    if (wN < 2) {
#pragma unroll
        for (int mt = 0; mt < 4; mt++) {
#pragma unroll
            for (int half = 0; half < 2; half++) {
                int row = wM * 64 + mt * 16 + half * 8 + gID;
#pragma unroll
                for (int nt = 0; nt < 4; nt++) {
                    int colL = wN * 32 + nt * 8 + 2 * tg;
                    float g0 = acc[mt][nt][half * 2 + 0] + bge[n0 + colL];
                    float g1 = acc[mt][nt][half * 2 + 1] + bge[n0 + colL + 1];
                    g0 = fminf(g0, LIMIT); g1 = fminf(g1, LIMIT);
                    float s0 = 1.f / (1.f + expf(-ALPHA * g0));
                    float s1 = 1.f / (1.f + expf(-ALPHA * g1));
                    sG[row * 68 + colL]     = g0 * s0;
                    sG[row * 68 + colL + 1] = g1 * s1;
                }
            }
        }
    }
    __syncthreads();
    if (wN >= 2) {
#pragma unroll
        for (int mt = 0; mt < 4; mt++) {
#pragma unroll
            for (int half = 0; half < 2; half++) {
                int row = wM * 64 + mt * 16 + half * 8 + gID;
                int slot = sSlot[row];
                if (slot < 0) continue;
                float* outp = g_act + (size_t)slot * IDIM;
#pragma unroll
                for (int nt = 0; nt < 4; nt++) {
                    int colL = (wN - 2) * 32 + nt * 8 + 2 * tg;
                    float u0 = acc[mt][nt][half * 2 + 0] + bge[IDIM + n0 + colL];
                    float u1 = acc[mt][nt][half * 2 + 1] + bge[IDIM + n0 + colL + 1];
                    u0 = fmaxf(fminf(u0, LIMIT), -LIMIT);
                    u1 = fmaxf(fminf(u1, LIMIT), -LIMIT);
                    float2 o = make_float2(
                        to_tf32f((u0 + 1.f) * sG[row * 68 + colL]),
                        to_tf32f((u1 + 1.f) * sG[row * 68 + colL + 1]));
                    *(float2*)(outp + n0 + colL) = o;
                }
            }
        }
    }
}

// =============== stage 2: down GEMM (N=128) + weighted atomic combine ===============
__global__ __launch_bounds__(256, 2) void down_mma(
    const float* __restrict__ Wd, const float* __restrict__ bd,
    float* __restrict__ out)
{
    int e   = blockIdx.z;
    int cnt = g_cnt[e];
    int m0  = blockIdx.y * 128;
    if (m0 >= cnt) return;
    int n0  = blockIdx.x * 128;

    extern __shared__ __align__(16) char dsm[];
    __shared__ int sSlot[128];

    int tid  = threadIdx.x;
    int wid  = tid >> 5, lane = tid & 31;
    int wM   = wid >> 2, wN = wid & 3;
    int gID  = lane >> 2, tg = lane & 3;

    for (int m = tid; m < 128; m += 256) {
        int idx = m0 + m;
        sSlot[m] = (idx < cnt) ? g_list[e * MAXP + idx] : -1;
    }
    __syncthreads();

    const float* We = Wd + (size_t)e * IDIM * HDIM;

    const float* aSrc[4]; int aSz[4]; uint32_t aDst[4];
#pragma unroll
    for (int i = 0; i < 4; i++) {
        int idx = tid + i * 256;
        int m = idx >> 3, kq = idx & 7;
        int slot = sSlot[m];
        aSrc[i] = (slot >= 0) ? g_act + (size_t)slot * IDIM + kq * 4 : g_act;
        aSz[i]  = (slot >= 0) ? 16 : 0;
        aDst[i] = (uint32_t)(m * A_STRIDE + kq * 4) * 4u;
    }
    const float* bSrc[4]; uint32_t bDst[4];
#pragma unroll
    for (int i = 0; i < 4; i++) {
        int idx = tid + i * 256;
        int k = idx >> 5, n4 = idx & 31;
        bSrc[i] = We + (size_t)k * HDIM + n0 + n4 * 4;
        bDst[i] = (uint32_t)(k * B_STRIDE + n4 * 4) * 4u;
    }

    float acc[4][4][4];
#pragma unroll
    for (int mt = 0; mt < 4; mt++)
#pragma unroll
        for (int nt = 0; nt < 4; nt++)
#pragma unroll
            for (int q = 0; q < 4; q++) acc[mt][nt][q] = 0.f;

    run_mainloop<false>(dsm, aSrc, aSz, aDst, bSrc, bDst, HDIM,
                        acc, wM, wN, lane);

    // ---- epilogue: weighted atomic accumulate ----
    const float* bde = bd + (size_t)e * HDIM;
#pragma unroll
    for (int mt = 0; mt < 4; mt++) {
#pragma unroll
        for (int half = 0; half < 2; half++) {
            int row = wM * 64 + mt * 16 + half * 8 + gID;
            int slot = sSlot[row];
            if (slot < 0) continue;
            float w = g_w[slot];
            float* outp = out + (size_t)(slot >> 1) * HDIM;
#pragma unroll
            for (int nt = 0; nt < 4; nt++) {
                int col = n0 + wN * 32 + nt * 8 + 2 * tg;
                atomicAdd(outp + col,     w * (acc[mt][nt][half * 2 + 0] + bde[col]));
                atomicAdd(outp + col + 1, w * (acc[mt][nt][half * 2 + 1] + bde[col + 1]));
            }
        }
    }
}

// ------------------------------ launch ------------------------------
extern "C" void kernel_launch(void* const* d_in, const int* in_sizes, int n_in,
                              void* d_out, int out_size)
{
    const float* x   = (const float*)d_in[0];
    const float* Wr  = (const float*)d_in[1];
    const float* br  = (const float*)d_in[2];
    const float* Wgu = (const float*)d_in[3];
    const float* bgu = (const float*)d_in[4];
    const float* Wd  = (const float*)d_in[5];
    const float* bd  = (const float*)d_in[6];
    float* out = (float*)d_out;

    cudaFuncSetAttribute(gu_mma,   cudaFuncAttributeMaxDynamicSharedMemorySize, SM_TOTAL);
    cudaFuncSetAttribute(down_mma, cudaFuncAttributeMaxDynamicSharedMemorySize, SM_TOTAL);

    init_kernel<<<(TTOK * HDIM / 4 + 255) / 256, 256>>>(out);
    router_kernel<<<TTOK / 8, 256>>>(x, Wr, br);

    dim3 ggrid(IDIM / 64, MAXP / 128, NEXP);    // (12, 32, 8)
    gu_mma<<<ggrid, 256, SM_TOTAL>>>(x, Wgu, bgu);

    dim3 dgrid(HDIM / 128, MAXP / 128, NEXP);   // (6, 32, 8)
    down_mma<<<dgrid, 256, SM_TOTAL>>>(Wd, bd, out);
}